// round 2
// baseline (speedup 1.0000x reference)
#include <cuda_runtime.h>

// RegRankLoss: pairwise ranking loss over N=8192 fp32 elements.
// loss = mean over {i<j, t_i != t_j} of softplus(-sign(t_i-t_j)*(p_i-p_j))
//
// Decomposition (td = t_i - t_j, pd = p_i - p_j, valid iff td != 0):
//   softplus(x) = max(x,0) + log1p(exp(-|x|)),  x = -sign(td)*pd, |x| = |pd|
//   max(x,0)    = (td*pd < 0) ? |pd| : 0
// Accumulate:
//   S1 = sum_valid log2(1 + exp2(-|pd| * log2(e)))   (ln2 applied at the end)
//   S2 = sum_{td*pd<0} |pd|
//   C  = #valid
//   loss = (ln2*S1 + S2) / C

#define TILE 256

__device__ double g_s1;
__device__ double g_s2;
__device__ unsigned long long g_cnt;

__device__ __forceinline__ float fast_ex2(float x) {
    float r;
    asm("ex2.approx.f32 %0, %1;" : "=f"(r) : "f"(x));
    return r;
}
__device__ __forceinline__ float fast_lg2(float x) {
    float r;
    asm("lg2.approx.f32 %0, %1;" : "=f"(r) : "f"(x));
    return r;
}

__global__ void rrl_init_kernel() {
    g_s1 = 0.0;
    g_s2 = 0.0;
    g_cnt = 0ull;
}

__global__ __launch_bounds__(TILE) void rrl_pair_kernel(
    const float* __restrict__ pred,
    const float* __restrict__ target,
    int n_tiles)
{
    // Map blockIdx.x -> (I, J) with I <= J over n_tiles row-tiles.
    int b = blockIdx.x;
    int I = 0;
    int rem = b;
    while (rem >= n_tiles - I) { rem -= n_tiles - I; ++I; }
    int J = I + rem;

    __shared__ float2 sj[TILE];

    int tid = threadIdx.x;
    int jg = J * TILE + tid;
    sj[tid] = make_float2(pred[jg], target[jg]);

    int ig = I * TILE + tid;
    float pi = pred[ig];
    float ti = target[ig];
    __syncthreads();

    const float NLOG2E = -1.44269504088896340736f;

    float acc_lg = 0.0f;   // sum of log2(1 + exp2(-|pd|*log2e))
    float acc_rl = 0.0f;   // sum of |pd| where td*pd < 0
    unsigned cnt = 0u;

    if (I == J) {
        // strict upper triangle within the tile: j > i (local)
        for (int j = tid + 1; j < TILE; ++j) {
            float2 v = sj[j];
            float pd = pi - v.x;
            float td = ti - v.y;
            float apd = fabsf(pd);
            float e  = fast_ex2(apd * NLOG2E);
            float lg = fast_lg2(1.0f + e);
            float prod = td * pd;
            if (td != 0.0f) { acc_lg += lg; cnt++; }
            if (prod < 0.0f) { acc_rl += apd; }
        }
    } else {
        #pragma unroll 4
        for (int j = 0; j < TILE; ++j) {
            float2 v = sj[j];           // broadcast across warp (conflict-free)
            float pd = pi - v.x;
            float td = ti - v.y;
            float apd = fabsf(pd);
            float e  = fast_ex2(apd * NLOG2E);
            float lg = fast_lg2(1.0f + e);
            float prod = td * pd;
            if (td != 0.0f) { acc_lg += lg; cnt++; }
            if (prod < 0.0f) { acc_rl += apd; }
        }
    }

    // ---- block reduction ----
    #pragma unroll
    for (int off = 16; off > 0; off >>= 1) {
        acc_lg += __shfl_down_sync(0xffffffffu, acc_lg, off);
        acc_rl += __shfl_down_sync(0xffffffffu, acc_rl, off);
        cnt    += __shfl_down_sync(0xffffffffu, cnt, off);
    }

    __shared__ float s_lg[8];
    __shared__ float s_rl[8];
    __shared__ unsigned s_ct[8];
    int wid = tid >> 5;
    int lid = tid & 31;
    if (lid == 0) { s_lg[wid] = acc_lg; s_rl[wid] = acc_rl; s_ct[wid] = cnt; }
    __syncthreads();

    if (wid == 0) {
        float a = (lid < 8) ? s_lg[lid] : 0.0f;
        float r = (lid < 8) ? s_rl[lid] : 0.0f;
        unsigned c = (lid < 8) ? s_ct[lid] : 0u;
        #pragma unroll
        for (int off = 4; off > 0; off >>= 1) {
            a += __shfl_down_sync(0xffffffffu, a, off);
            r += __shfl_down_sync(0xffffffffu, r, off);
            c += __shfl_down_sync(0xffffffffu, c, off);
        }
        if (lid == 0) {
            atomicAdd(&g_s1, (double)a);
            atomicAdd(&g_s2, (double)r);
            atomicAdd(&g_cnt, (unsigned long long)c);
        }
    }
}

__global__ void rrl_final_kernel(float* __restrict__ out) {
    const double LN2 = 0.69314718055994530942;
    unsigned long long c = g_cnt;
    double s = LN2 * g_s1 + g_s2;
    out[0] = (c > 0ull) ? (float)(s / (double)c) : 0.0f;
}

extern "C" void kernel_launch(void* const* d_in, const int* in_sizes, int n_in,
                              void* d_out, int out_size) {
    const float* pred   = (const float*)d_in[0];
    const float* target = (const float*)d_in[1];
    float* out = (float*)d_out;

    int n = in_sizes[0];
    int n_tiles = n / TILE;                      // n = 8192 -> 32
    int n_blocks = n_tiles * (n_tiles + 1) / 2;  // 528

    rrl_init_kernel<<<1, 1>>>();
    rrl_pair_kernel<<<n_blocks, TILE>>>(pred, target, n_tiles);
    rrl_final_kernel<<<1, 1>>>(out);
}